// round 9
// baseline (speedup 1.0000x reference)
#include <cuda_runtime.h>
#include <math_constants.h>

#define H_IN   256
#define W_IN   256
#define H_OUT  128
#define W_OUT  128
#define NEG_INF (-CUDART_INF_F)

// One lane owns 8 input cols: a = cols 8l..8l+3, b = cols 8l+4..8l+7.
// Warp spans the full 256-col row -> shuffle edges are true image borders.
struct Row8 { float4 a, b; };

__device__ __forceinline__ Row8 ldrow(const float* __restrict__ fp, int r, int c)
{
    Row8 x;
    x.a = make_float4(NEG_INF, NEG_INF, NEG_INF, NEG_INF);
    x.b = x.a;
    if ((unsigned)r < (unsigned)H_IN) {
        const float* rp = fp + r * W_IN + c;
        x.a = *(const float4*)(rp);
        x.b = *(const float4*)(rp + 4);
    }
    return x;
}

// Horizontal 7-tap max-plus: 4 output cols (centers 8l, 8l+2, 8l+4, 8l+6).
__device__ __forceinline__ float4 hmax(const Row8& x, int lane,
                                       float h1, float h2, float h3)
{
    float m3 = __shfl_up_sync(0xffffffffu, x.b.y, 1);   // col 8l-3
    float m2 = __shfl_up_sync(0xffffffffu, x.b.z, 1);   // col 8l-2
    float m1 = __shfl_up_sync(0xffffffffu, x.b.w, 1);   // col 8l-1
    float p8 = __shfl_down_sync(0xffffffffu, x.a.x, 1); // col 8l+8
    float p9 = __shfl_down_sync(0xffffffffu, x.a.y, 1); // col 8l+9
    if (lane == 0)  { m3 = NEG_INF; m2 = NEG_INF; m1 = NEG_INF; }
    if (lane == 31) { p8 = NEG_INF; p9 = NEG_INF; }

    float4 g;
    g.x = fmaxf(fmaxf(x.a.x,                    fmaxf(m1,    x.a.y) + h1),
                fmaxf(fmaxf(m2,    x.a.z) + h2, fmaxf(m3,    x.a.w) + h3));
    g.y = fmaxf(fmaxf(x.a.z,                    fmaxf(x.a.y, x.a.w) + h1),
                fmaxf(fmaxf(x.a.x, x.b.x) + h2, fmaxf(m1,    x.b.y) + h3));
    g.z = fmaxf(fmaxf(x.b.x,                    fmaxf(x.a.w, x.b.y) + h1),
                fmaxf(fmaxf(x.a.z, x.b.z) + h2, fmaxf(x.a.y, x.b.w) + h3));
    g.w = fmaxf(fmaxf(x.b.z,                    fmaxf(x.b.y, x.b.w) + h1),
                fmaxf(fmaxf(x.b.x, p8)    + h2, fmaxf(x.a.w, p9)    + h3));
    return g;
}

// Vertical 7-tap: center slot s0 (compile-time literal at every call site).
__device__ __forceinline__ float4 vmax(const float4* ring, int s0,
                                       float h1, float h2, float h3)
{
    float4 c  = ring[s0 & 7];
    float4 a1 = ring[(s0 + 7) & 7], b1 = ring[(s0 + 1) & 7];
    float4 a2 = ring[(s0 + 6) & 7], b2 = ring[(s0 + 2) & 7];
    float4 a3 = ring[(s0 + 5) & 7], b3 = ring[(s0 + 3) & 7];
    float4 o;
    o.x = fmaxf(fmaxf(c.x, fmaxf(a1.x, b1.x) + h1),
                fmaxf(fmaxf(a2.x, b2.x) + h2, fmaxf(a3.x, b3.x) + h3));
    o.y = fmaxf(fmaxf(c.y, fmaxf(a1.y, b1.y) + h1),
                fmaxf(fmaxf(a2.y, b2.y) + h2, fmaxf(a3.y, b3.y) + h3));
    o.z = fmaxf(fmaxf(c.z, fmaxf(a1.z, b1.z) + h1),
                fmaxf(fmaxf(a2.z, b2.z) + h2, fmaxf(a3.z, b3.z) + h3));
    o.w = fmaxf(fmaxf(c.w, fmaxf(a1.w, b1.w) + h1),
                fmaxf(fmaxf(a2.w, b2.w) + h2, fmaxf(a3.w, b3.w) + h3));
    return o;
}

__global__ __launch_bounds__(128)
void parabolic_pool_kernel(const float* __restrict__ f,
                           const float* __restrict__ tptr,
                           float* __restrict__ out)
{
    // one warp per (plane, 64-row strip); warp spans the full 256-col width
    const int gw    = blockIdx.x * 4 + (threadIdx.x >> 5);   // 0..4095
    const int lane  = threadIdx.x & 31;
    const int plane = gw >> 1;
    const int i0    = (gw & 1) * 64;             // output row strip origin
    const int cb    = 8 * lane;                  // lane's input col base
    const int r0    = 2 * i0;                    // input row base of strip

    const float* __restrict__ fp = f + (size_t)plane * (H_IN * W_IN);
    float* __restrict__ op = out + (size_t)plane * (H_OUT * W_OUT)
                                 + (size_t)i0 * W_OUT + 4 * lane;

    const float inv4t = 0.25f / tptr[0];
    const float h1 = -1.0f * inv4t;
    const float h2 = -4.0f * inv4t;
    const float h3 = -9.0f * inv4t;

    // ring[(local input row) & 7] = horizontal max-plus of that row
    float4 ring[8];

    // ---- prologue: local rows -3..3 -> slots 5,6,7,0,1,2,3 (slot 4 unused) ----
#pragma unroll
    for (int k = 0; k < 7; ++k) {
        Row8 x = ldrow(fp, r0 - 3 + k, cb);
        ring[(k + 5) & 7] = hmax(x, lane, h1, h2, h3);
    }

    // 4-row prefetch: local rows 4,5,6,7 (always in range)
    Row8 pv0 = ldrow(fp, r0 + 4, cb);
    Row8 pv1 = ldrow(fp, r0 + 5, cb);
    Row8 pv2 = ldrow(fp, r0 + 6, cb);
    Row8 pv3 = ldrow(fp, r0 + 7, cb);

    // ---- main: j = 0..29 output-row pairs (2 outputs, 4 input rows per j) ----
    // pv consumed in place (hmax) then reloaded: no copies, deep MLP.
#pragma unroll 2
    for (int j = 0; j < 30; ++j) {
        const int s = (4 * j) & 7;               // 0 for even j, 4 for odd j
        const int rb = r0 + 4 * j;               // center input row of out[2j]

        float4 o0 = vmax(ring, s, h1, h2, h3);   // window rows 4j-3..4j+3
        *(float4*)(op + (2 * j) * W_OUT) = o0;

        ring[(s + 4) & 7] = hmax(pv0, lane, h1, h2, h3);   // row 4j+4
        ring[(s + 5) & 7] = hmax(pv1, lane, h1, h2, h3);   // row 4j+5
        pv0 = ldrow(fp, rb + 8, cb);
        pv1 = ldrow(fp, rb + 9, cb);

        float4 o1 = vmax(ring, (s + 2) & 7, h1, h2, h3);   // rows 4j-1..4j+5
        *(float4*)(op + (2 * j + 1) * W_OUT) = o1;

        ring[(s + 6) & 7] = hmax(pv2, lane, h1, h2, h3);   // row 4j+6
        ring[(s + 7) & 7] = hmax(pv3, lane, h1, h2, h3);   // row 4j+7
        pv2 = ldrow(fp, rb + 10, cb);
        pv3 = ldrow(fp, rb + 11, cb);
    }

    // ---- tail j = 30 (even; only rows 128,129 still needed) ----
    {
        float4 o0 = vmax(ring, 0, h1, h2, h3);
        *(float4*)(op + 60 * W_OUT) = o0;
        ring[4] = hmax(pv0, lane, h1, h2, h3);   // row 124
        ring[5] = hmax(pv1, lane, h1, h2, h3);   // row 125
        pv0 = ldrow(fp, r0 + 128, cb);           // guarded for top strip only
        pv1 = ldrow(fp, r0 + 129, cb);
        float4 o1 = vmax(ring, 2, h1, h2, h3);
        *(float4*)(op + 61 * W_OUT) = o1;
        ring[6] = hmax(pv2, lane, h1, h2, h3);   // row 126
        ring[7] = hmax(pv3, lane, h1, h2, h3);   // row 127
    }
    // ---- tail j = 31 (odd; consume only) ----
    {
        float4 o0 = vmax(ring, 4, h1, h2, h3);   // rows 121..127
        *(float4*)(op + 62 * W_OUT) = o0;
        ring[0] = hmax(pv0, lane, h1, h2, h3);   // row 128
        ring[1] = hmax(pv1, lane, h1, h2, h3);   // row 129
        float4 o1 = vmax(ring, 6, h1, h2, h3);   // rows 123..129
        *(float4*)(op + 63 * W_OUT) = o1;
    }
}

extern "C" void kernel_launch(void* const* d_in, const int* in_sizes, int n_in,
                              void* d_out, int out_size)
{
    const float* f = (const float*)d_in[0];
    const float* t = (const float*)d_in[1];
    float* out = (float*)d_out;

    // 2048 planes x 2 row-strips = 4096 warps = 1024 blocks x 4 warps
    parabolic_pool_kernel<<<1024, 128>>>(f, t, out);
}

// round 10
// speedup vs baseline: 1.1692x; 1.1692x over previous
#include <cuda_runtime.h>
#include <math_constants.h>

#define H_IN   256
#define W_IN   256
#define H_OUT  128
#define W_OUT  128
#define NEG_INF (-CUDART_INF_F)

// One lane owns 8 input cols: a = cols 8l..8l+3, b = cols 8l+4..8l+7.
// A warp spans the full 256-col row -> shuffle edges are true image borders,
// so there are NO edge-patch loads at all.
struct Row8 { float4 a, b; };

__device__ __forceinline__ Row8 ldrow(const float* __restrict__ fp, int r, int c)
{
    Row8 x;
    x.a = make_float4(NEG_INF, NEG_INF, NEG_INF, NEG_INF);
    x.b = x.a;
    if ((unsigned)r < (unsigned)H_IN) {
        const float* rp = fp + r * W_IN + c;
        x.a = __ldcs((const float4*)(rp));       // streaming: evict-first
        x.b = __ldcs((const float4*)(rp + 4));
    }
    return x;
}

// Horizontal 7-tap max-plus: 4 output cols (centers 8l, 8l+2, 8l+4, 8l+6).
// Symmetric weights h[o] = -o^2/(4t): pair-max then single add.
__device__ __forceinline__ float4 hmax(const Row8& x, int lane,
                                       float h1, float h2, float h3)
{
    float m3 = __shfl_up_sync(0xffffffffu, x.b.y, 1);   // col 8l-3
    float m2 = __shfl_up_sync(0xffffffffu, x.b.z, 1);   // col 8l-2
    float m1 = __shfl_up_sync(0xffffffffu, x.b.w, 1);   // col 8l-1
    float p8 = __shfl_down_sync(0xffffffffu, x.a.x, 1); // col 8l+8
    float p9 = __shfl_down_sync(0xffffffffu, x.a.y, 1); // col 8l+9
    if (lane == 0)  { m3 = NEG_INF; m2 = NEG_INF; m1 = NEG_INF; }
    if (lane == 31) { p8 = NEG_INF; p9 = NEG_INF; }

    float4 g;
    g.x = fmaxf(fmaxf(x.a.x,                    fmaxf(m1,    x.a.y) + h1),
                fmaxf(fmaxf(m2,    x.a.z) + h2, fmaxf(m3,    x.a.w) + h3));
    g.y = fmaxf(fmaxf(x.a.z,                    fmaxf(x.a.y, x.a.w) + h1),
                fmaxf(fmaxf(x.a.x, x.b.x) + h2, fmaxf(m1,    x.b.y) + h3));
    g.z = fmaxf(fmaxf(x.b.x,                    fmaxf(x.a.w, x.b.y) + h1),
                fmaxf(fmaxf(x.a.z, x.b.z) + h2, fmaxf(x.a.y, x.b.w) + h3));
    g.w = fmaxf(fmaxf(x.b.z,                    fmaxf(x.b.y, x.b.w) + h1),
                fmaxf(fmaxf(x.b.x, p8)    + h2, fmaxf(x.a.w, p9)    + h3));
    return g;
}

__device__ __forceinline__ float4 vmax(const float4* ring, int s0,
                                       float h1, float h2, float h3)
{
    float4 c  = ring[s0 & 7];
    float4 a1 = ring[(s0 + 7) & 7], b1 = ring[(s0 + 1) & 7];
    float4 a2 = ring[(s0 + 6) & 7], b2 = ring[(s0 + 2) & 7];
    float4 a3 = ring[(s0 + 5) & 7], b3 = ring[(s0 + 3) & 7];
    float4 o;
    o.x = fmaxf(fmaxf(c.x, fmaxf(a1.x, b1.x) + h1),
                fmaxf(fmaxf(a2.x, b2.x) + h2, fmaxf(a3.x, b3.x) + h3));
    o.y = fmaxf(fmaxf(c.y, fmaxf(a1.y, b1.y) + h1),
                fmaxf(fmaxf(a2.y, b2.y) + h2, fmaxf(a3.y, b3.y) + h3));
    o.z = fmaxf(fmaxf(c.z, fmaxf(a1.z, b1.z) + h1),
                fmaxf(fmaxf(a2.z, b2.z) + h2, fmaxf(a3.z, b3.z) + h3));
    o.w = fmaxf(fmaxf(c.w, fmaxf(a1.w, b1.w) + h1),
                fmaxf(fmaxf(a2.w, b2.w) + h2, fmaxf(a3.w, b3.w) + h3));
    return o;
}

__global__ __launch_bounds__(128)
void parabolic_pool_kernel(const float* __restrict__ f,
                           const float* __restrict__ tptr,
                           float* __restrict__ out)
{
    // one warp per (plane, 64-row strip); warp spans the full 256-col width
    const int gw    = blockIdx.x * 4 + (threadIdx.x >> 5);   // 0..4095
    const int lane  = threadIdx.x & 31;
    const int plane = gw >> 1;
    const int i0    = (gw & 1) * 64;             // output row strip origin
    const int cb    = 8 * lane;                  // lane's input col base

    const float* __restrict__ fp = f + (size_t)plane * (H_IN * W_IN);
    float* __restrict__ op = out + (size_t)plane * (H_OUT * W_OUT)
                                 + (size_t)i0 * W_OUT + 4 * lane;

    const float inv4t = 0.25f / tptr[0];
    const float h1 = -1.0f * inv4t;
    const float h2 = -4.0f * inv4t;
    const float h3 = -9.0f * inv4t;

    // ring[R & 7] = horizontal max-plus of input row R
    float4 ring[8];

    // ---- prologue: input rows 2*i0-3 .. 2*i0+3 ----
#pragma unroll
    for (int k = 0; k < 7; ++k) {
        Row8 x = ldrow(fp, 2 * i0 - 3 + k, cb);
        ring[(k + 5) & 7] = hmax(x, lane, h1, h2, h3);
    }

    // 2-row prefetch: rows 2*i0+4, 2*i0+5 (always in range)
    Row8 pva = ldrow(fp, 2 * i0 + 4, cb);
    Row8 pvb = ldrow(fp, 2 * i0 + 5, cb);

    // ---- body: 64 output rows, unrolled x4 (static ring indices) ----
    for (int ib = 0; ib < 16; ++ib) {
#pragma unroll
        for (int ip = 0; ip < 4; ++ip) {
            const int i = ib * 4 + ip;                  // local output row

            // vertical max-plus (center input row 2*(i0+i) -> slot 2*ip) + store
            float4 o = vmax(ring, 2 * ip, h1, h2, h3);
            __stcs((float4*)(op + i * W_OUT), o);       // streaming store

            // rotate prefetched rows into the pipeline, issue next loads
            Row8 na = pva, nb = pvb;
            const int rn = 2 * (i0 + i) + 6;
            pva = ldrow(fp, rn,     cb);
            pvb = ldrow(fp, rn + 1, cb);

            ring[(2 * ip + 4) & 7] = hmax(na, lane, h1, h2, h3);
            ring[(2 * ip + 5) & 7] = hmax(nb, lane, h1, h2, h3);
        }
    }
}

extern "C" void kernel_launch(void* const* d_in, const int* in_sizes, int n_in,
                              void* d_out, int out_size)
{
    const float* f = (const float*)d_in[0];
    const float* t = (const float*)d_in[1];
    float* out = (float*)d_out;

    // 2048 planes x 2 row-strips = 4096 warps = 1024 blocks x 4 warps
    parabolic_pool_kernel<<<1024, 128>>>(f, t, out);
}